// round 14
// baseline (speedup 1.0000x reference)
#include <cuda_runtime.h>
#include <cstdint>

// DepConv3D R14: 8px (4x * 2y) x 8oc per thread, pixel-pair FFMA2 lanes,
// slice-summed accumulators (32 ull regs). Loop ky->kx->i; 8 gate words per
// (ky,kx); each uniform weight LDS.128 feeds 8 FFMA2. ky-phased dup-weight
// staging (24.6KB). 3 CTAs/SM.

#define CCH 16
#define HH 512
#define WW 512
#define OCC 32
#define TW 64
#define TH 8
#define FT_ROWS 10
#define SPITCH 68                        // floats per row; c <-> gx = x0+c-1
#define SWK_ENT (16*3*2*16)              // per-ky float4 entries = 1536 (24576 B)
#define SW_ENT  (3*SWK_ENT)
#define SF_FLOATS (CCH*FT_ROWS*SPITCH)   // 10880
#define SD_INTS (FT_ROWS*SPITCH)         // 680
#define SMEM_TOTAL (SWK_ENT*16 + SF_FLOATS*4 + SD_INTS*4)   // 70816

typedef unsigned long long ull;

__device__ float4 g_wd[SW_ENT];

__global__ void pack_weights_kernel(const float* __restrict__ wgt)
{
    // idx = ((ky*16+i)*3+kx)*32 + s*16 + e
    int idx = blockIdx.x * blockDim.x + threadIdx.x;
    if (idx < SW_ENT) {
        int e  = idx & 15;
        int s  = (idx >> 4) & 1;
        int kx = (idx >> 5) % 3;
        int i  = (idx / 96) & 15;
        int ky = idx / 1536;
        int k = ky * 3 + kx;
        float w0 = wgt[(((2 * e)     * CCH + i) * 3 + s) * 9 + k];
        float w1 = wgt[(((2 * e + 1) * CCH + i) * 3 + s) * 9 + k];
        g_wd[idx] = make_float4(w0, w0, w1, w1);
    }
}

__global__ __launch_bounds__(256, 3)
void depconv3d_kernel(const float* __restrict__ feat,
                      const int*   __restrict__ depth,
                      float* __restrict__ out)
{
    extern __shared__ char smem[];
    float4* sWk = (float4*)smem;                         // [i][kx][s][e]
    float*  sF  = (float*)(smem + SWK_ENT * 16);         // [i][r][c]
    int*    sD  = (int*)(smem + SWK_ENT * 16 + SF_FLOATS * 4);

    const int tx = threadIdx.x;        // 0..15 -> x = x0 + 4*tx + (0..3)
    const int ty = threadIdx.y;        // 0..3  -> rows y0 + 2*ty + (0..1)
    const int tz = threadIdx.z;        // 0..3  -> oc 8*tz..8*tz+7 (uniform)
    const int tid = tx + 16 * ty + 64 * tz;
    const int b  = blockIdx.z;
    const int y0 = blockIdx.y * TH;
    const int x0 = blockIdx.x * TW;

    // ---- depth tile ----
    for (int idx = tid; idx < SD_INTS; idx += 256) {
        int r = idx / SPITCH, c = idx - r * SPITCH;
        int gy = y0 + r - 1, gx = x0 + c - 1;
        int d = 0;
        if (gy >= 0 && gy < HH && gx >= 0 && gx < WW && c < 66)
            d = depth[(b * HH + gy) * WW + gx];
        sD[idx] = d;
    }

    // ---- feature tiles ----
    for (int idx = tid; idx < SF_FLOATS; idx += 256) {
        int c = idx % SPITCH;
        int r = (idx / SPITCH) % FT_ROWS;
        int i = idx / (SPITCH * FT_ROWS);
        int gy = y0 + r - 1, gx = x0 + c - 1;
        float v = 0.f;
        if (gy >= 0 && gy < HH && gx >= 0 && gx < WW && c < 66)
            v = feat[((size_t)(b * CCH + i) * HH + gy) * WW + gx];
        sF[idx] = v;
    }
    __syncthreads();

    // ---- masks: mm[rr*4+p] = mA | (mB<<16) for px (row 2ty+rr, x 4tx+p) ----
    unsigned mm[8];
    #pragma unroll
    for (int rr = 0; rr < 2; rr++)
        #pragma unroll
        for (int p = 0; p < 4; p++) {
            int dc = sD[(2 * ty + rr + 1) * SPITCH + 4 * tx + p + 1];
            unsigned a = 0, bm = 0;
            #pragma unroll
            for (int k = 0; k < 9; k++) {
                int ky = k / 3, kx = k - ky * 3;
                int dn = sD[(2 * ty + rr + ky) * SPITCH + 4 * tx + p + kx];
                a  |= (unsigned)(dn == dc - 1) << k;
                bm |= (unsigned)(dn == dc)     << k;
            }
            mm[rr * 4 + p] = a | (bm << 16);
        }

    ull acc[4][8];                     // [rq = rr*2+q][local oc]; lanes=(px2q,px2q+1)
    #pragma unroll
    for (int rq = 0; rq < 4; rq++)
        #pragma unroll
        for (int o = 0; o < 8; o++) acc[rq][o] = 0ull;

    const unsigned fw0 = (unsigned)__cvta_generic_to_shared(sF)
                       + (unsigned)((2 * ty * SPITCH + 4 * tx) * 4);
    const unsigned ww0 = (unsigned)__cvta_generic_to_shared(sWk)
                       + (unsigned)(4 * tz) * 16u;      // e base = 4*tz

    #pragma unroll 1
    for (int ky = 0; ky < 3; ky++) {
        __syncthreads();
        #pragma unroll
        for (int it = 0; it < 6; it++)
            sWk[tid + it * 256] = g_wd[ky * SWK_ENT + tid + it * 256];
        __syncthreads();

        #pragma unroll
        for (int kx = 0; kx < 3; kx++) {
            const int k = ky * 3 + kx;
            ull MA[4], MB[4];
            #pragma unroll
            for (int rq = 0; rq < 4; rq++) {
                unsigned lo = mm[(rq >> 1) * 4 + (rq & 1) * 2];
                unsigned hi = mm[(rq >> 1) * 4 + (rq & 1) * 2 + 1];
                unsigned aL = 0u - ((lo >> k) & 1u);
                unsigned aH = 0u - ((hi >> k) & 1u);
                unsigned bL = 0u - ((lo >> (k + 16)) & 1u);
                unsigned bH = 0u - ((hi >> (k + 16)) & 1u);
                MA[rq] = ((ull)aH << 32) | aL;
                MB[rq] = ((ull)bH << 32) | bL;
            }

            unsigned fa = fw0 + (unsigned)(ky * SPITCH * 4);
            unsigned wa = ww0 + (unsigned)(kx * 512);

            #pragma unroll 1
            for (int i = 0; i < CCH; i++) {
                // two rows, 6-float windows f0..f5 at cols 4tx..4tx+5
                ull Pa01, Pa23, Pa45, Pb01, Pb23, Pb45;
                asm("ld.shared.v2.b64 {%0,%1},[%2];" : "=l"(Pa01), "=l"(Pa23) : "r"(fa));
                asm("ld.shared.b64 %0,[%1];" : "=l"(Pa45) : "r"(fa + 16));
                asm("ld.shared.v2.b64 {%0,%1},[%2];" : "=l"(Pb01), "=l"(Pb23) : "r"(fa + SPITCH * 4));
                asm("ld.shared.b64 %0,[%1];" : "=l"(Pb45) : "r"(fa + SPITCH * 4 + 16));

                ull Q[4];   // [rq]: pair values at this kx
                if (kx == 0) { Q[0] = Pa01; Q[1] = Pa23; Q[2] = Pb01; Q[3] = Pb23; }
                else if (kx == 2) { Q[0] = Pa23; Q[1] = Pa45; Q[2] = Pb23; Q[3] = Pb45; }
                else {
                    unsigned a0,a1,a2,a3,a4,a5,b0,b1,b2,b3,b4,b5;
                    asm("mov.b64 {%0,%1},%2;" : "=r"(a0), "=r"(a1) : "l"(Pa01));
                    asm("mov.b64 {%0,%1},%2;" : "=r"(a2), "=r"(a3) : "l"(Pa23));
                    asm("mov.b64 {%0,%1},%2;" : "=r"(a4), "=r"(a5) : "l"(Pa45));
                    asm("mov.b64 {%0,%1},%2;" : "=r"(b0), "=r"(b1) : "l"(Pb01));
                    asm("mov.b64 {%0,%1},%2;" : "=r"(b2), "=r"(b3) : "l"(Pb23));
                    asm("mov.b64 {%0,%1},%2;" : "=r"(b4), "=r"(b5) : "l"(Pb45));
                    asm("mov.b64 %0,{%1,%2};" : "=l"(Q[0]) : "r"(a1), "r"(a2));
                    asm("mov.b64 %0,{%1,%2};" : "=l"(Q[1]) : "r"(a3), "r"(a4));
                    asm("mov.b64 %0,{%1,%2};" : "=l"(Q[2]) : "r"(b1), "r"(b2));
                    asm("mov.b64 %0,{%1,%2};" : "=l"(Q[3]) : "r"(b3), "r"(b4));
                }

                ull GA0 = Q[0] & MA[0], GA1 = Q[1] & MA[1];
                ull GA2 = Q[2] & MA[2], GA3 = Q[3] & MA[3];
                ull GB0 = Q[0] & MB[0], GB1 = Q[1] & MB[1];
                ull GB2 = Q[2] & MB[2], GB3 = Q[3] & MB[3];

                #pragma unroll
                for (int j = 0; j < 4; j++) {     // slice A (s=0)
                    ull u, v;
                    asm("ld.shared.v2.b64 {%0,%1},[%2];"
                        : "=l"(u), "=l"(v) : "r"(wa + (unsigned)(j * 16)));
                    asm("fma.rn.f32x2 %0,%1,%2,%0;" : "+l"(acc[0][2*j])   : "l"(GA0), "l"(u));
                    asm("fma.rn.f32x2 %0,%1,%2,%0;" : "+l"(acc[0][2*j+1]) : "l"(GA0), "l"(v));
                    asm("fma.rn.f32x2 %0,%1,%2,%0;" : "+l"(acc[1][2*j])   : "l"(GA1), "l"(u));
                    asm("fma.rn.f32x2 %0,%1,%2,%0;" : "+l"(acc[1][2*j+1]) : "l"(GA1), "l"(v));
                    asm("fma.rn.f32x2 %0,%1,%2,%0;" : "+l"(acc[2][2*j])   : "l"(GA2), "l"(u));
                    asm("fma.rn.f32x2 %0,%1,%2,%0;" : "+l"(acc[2][2*j+1]) : "l"(GA2), "l"(v));
                    asm("fma.rn.f32x2 %0,%1,%2,%0;" : "+l"(acc[3][2*j])   : "l"(GA3), "l"(u));
                    asm("fma.rn.f32x2 %0,%1,%2,%0;" : "+l"(acc[3][2*j+1]) : "l"(GA3), "l"(v));
                }
                #pragma unroll
                for (int j = 0; j < 4; j++) {     // slice B (s=1, +256B)
                    ull u, v;
                    asm("ld.shared.v2.b64 {%0,%1},[%2];"
                        : "=l"(u), "=l"(v) : "r"(wa + (unsigned)(256 + j * 16)));
                    asm("fma.rn.f32x2 %0,%1,%2,%0;" : "+l"(acc[0][2*j])   : "l"(GB0), "l"(u));
                    asm("fma.rn.f32x2 %0,%1,%2,%0;" : "+l"(acc[0][2*j+1]) : "l"(GB0), "l"(v));
                    asm("fma.rn.f32x2 %0,%1,%2,%0;" : "+l"(acc[1][2*j])   : "l"(GB1), "l"(u));
                    asm("fma.rn.f32x2 %0,%1,%2,%0;" : "+l"(acc[1][2*j+1]) : "l"(GB1), "l"(v));
                    asm("fma.rn.f32x2 %0,%1,%2,%0;" : "+l"(acc[2][2*j])   : "l"(GB2), "l"(u));
                    asm("fma.rn.f32x2 %0,%1,%2,%0;" : "+l"(acc[2][2*j+1]) : "l"(GB2), "l"(v));
                    asm("fma.rn.f32x2 %0,%1,%2,%0;" : "+l"(acc[3][2*j])   : "l"(GB3), "l"(u));
                    asm("fma.rn.f32x2 %0,%1,%2,%0;" : "+l"(acc[3][2*j+1]) : "l"(GB3), "l"(v));
                }
                fa += FT_ROWS * SPITCH * 4;     // next channel (2720 B)
                wa += 1536;                     // next i block (96 entries)
            }
        }
    }

    // ---- epilogue: row rr, cols 4tx..4tx+3 from pairs (rr*2, rr*2+1) ----
    const int gx = x0 + 4 * tx;
    #pragma unroll
    for (int o = 0; o < 8; o++)
        #pragma unroll
        for (int rr = 0; rr < 2; rr++) {
            float2 q0 = *reinterpret_cast<float2*>(&acc[rr * 2][o]);
            float2 q1 = *reinterpret_cast<float2*>(&acc[rr * 2 + 1][o]);
            float4 st = make_float4(q0.x, q0.y, q1.x, q1.y);
            int gy = y0 + 2 * ty + rr;
            size_t off = (((size_t)(b * OCC + 8 * tz + o) * HH + gy) * WW) + gx;
            *reinterpret_cast<float4*>(out + off) = st;
        }
}

extern "C" void kernel_launch(void* const* d_in, const int* in_sizes, int n_in,
                              void* d_out, int out_size)
{
    const float* feat  = (const float*)d_in[0];
    const int*   depth = (const int*)d_in[1];
    const float* wgt   = (const float*)d_in[2];
    float* out = (float*)d_out;

    cudaFuncSetAttribute(depconv3d_kernel,
                         cudaFuncAttributeMaxDynamicSharedMemorySize, SMEM_TOTAL);

    pack_weights_kernel<<<(SW_ENT + 255) / 256, 256>>>(wgt);

    dim3 block(16, 4, 4);
    dim3 grid(WW / TW, HH / TH, 4);
    depconv3d_kernel<<<grid, block, SMEM_TOTAL>>>(feat, depth, out);
}

// round 16
// speedup vs baseline: 3.4944x; 3.4944x over previous
#include <cuda_runtime.h>
#include <cstdint>

// DepConv3D R15 (= R14 at 128 regs): 8px (4x * 2y) x 8oc per thread,
// pixel-pair FFMA2 lanes, slice-summed accumulators (acc[4][8] = 64 regs —
// R14's 80-reg cap spilled these; launch_bounds(256,2) gives them room).
// Loop ky->kx->i; each uniform weight LDS.128 feeds 8 FFMA2 across
// independent accumulators. ky-phased dup-weight staging (24.6 KB).

#define CCH 16
#define HH 512
#define WW 512
#define OCC 32
#define TW 64
#define TH 8
#define FT_ROWS 10
#define SPITCH 68                        // floats per row; c <-> gx = x0+c-1
#define SWK_ENT (16*3*2*16)              // per-ky float4 entries = 1536 (24576 B)
#define SW_ENT  (3*SWK_ENT)
#define SF_FLOATS (CCH*FT_ROWS*SPITCH)   // 10880
#define SD_INTS (FT_ROWS*SPITCH)         // 680
#define SMEM_TOTAL (SWK_ENT*16 + SF_FLOATS*4 + SD_INTS*4)   // 70816

typedef unsigned long long ull;

__device__ float4 g_wd[SW_ENT];

__global__ void pack_weights_kernel(const float* __restrict__ wgt)
{
    // idx = ((ky*16+i)*3+kx)*32 + s*16 + e
    int idx = blockIdx.x * blockDim.x + threadIdx.x;
    if (idx < SW_ENT) {
        int e  = idx & 15;
        int s  = (idx >> 4) & 1;
        int kx = (idx >> 5) % 3;
        int i  = (idx / 96) & 15;
        int ky = idx / 1536;
        int k = ky * 3 + kx;
        float w0 = wgt[(((2 * e)     * CCH + i) * 3 + s) * 9 + k];
        float w1 = wgt[(((2 * e + 1) * CCH + i) * 3 + s) * 9 + k];
        g_wd[idx] = make_float4(w0, w0, w1, w1);
    }
}

__global__ __launch_bounds__(256, 2)
void depconv3d_kernel(const float* __restrict__ feat,
                      const int*   __restrict__ depth,
                      float* __restrict__ out)
{
    extern __shared__ char smem[];
    float4* sWk = (float4*)smem;                         // [i][kx][s][e]
    float*  sF  = (float*)(smem + SWK_ENT * 16);         // [i][r][c]
    int*    sD  = (int*)(smem + SWK_ENT * 16 + SF_FLOATS * 4);

    const int tx = threadIdx.x;        // 0..15 -> x = x0 + 4*tx + (0..3)
    const int ty = threadIdx.y;        // 0..3  -> rows y0 + 2*ty + (0..1)
    const int tz = threadIdx.z;        // 0..3  -> oc 8*tz..8*tz+7 (uniform)
    const int tid = tx + 16 * ty + 64 * tz;
    const int b  = blockIdx.z;
    const int y0 = blockIdx.y * TH;
    const int x0 = blockIdx.x * TW;

    // ---- depth tile ----
    for (int idx = tid; idx < SD_INTS; idx += 256) {
        int r = idx / SPITCH, c = idx - r * SPITCH;
        int gy = y0 + r - 1, gx = x0 + c - 1;
        int d = 0;
        if (gy >= 0 && gy < HH && gx >= 0 && gx < WW && c < 66)
            d = depth[(b * HH + gy) * WW + gx];
        sD[idx] = d;
    }

    // ---- feature tiles ----
    for (int idx = tid; idx < SF_FLOATS; idx += 256) {
        int c = idx % SPITCH;
        int r = (idx / SPITCH) % FT_ROWS;
        int i = idx / (SPITCH * FT_ROWS);
        int gy = y0 + r - 1, gx = x0 + c - 1;
        float v = 0.f;
        if (gy >= 0 && gy < HH && gx >= 0 && gx < WW && c < 66)
            v = feat[((size_t)(b * CCH + i) * HH + gy) * WW + gx];
        sF[idx] = v;
    }
    __syncthreads();

    // ---- masks: mm[rr*4+p] = mA | (mB<<16) for px (row 2ty+rr, x 4tx+p) ----
    unsigned mm[8];
    #pragma unroll
    for (int rr = 0; rr < 2; rr++)
        #pragma unroll
        for (int p = 0; p < 4; p++) {
            int dc = sD[(2 * ty + rr + 1) * SPITCH + 4 * tx + p + 1];
            unsigned a = 0, bm = 0;
            #pragma unroll
            for (int k = 0; k < 9; k++) {
                int ky = k / 3, kx = k - ky * 3;
                int dn = sD[(2 * ty + rr + ky) * SPITCH + 4 * tx + p + kx];
                a  |= (unsigned)(dn == dc - 1) << k;
                bm |= (unsigned)(dn == dc)     << k;
            }
            mm[rr * 4 + p] = a | (bm << 16);
        }

    ull acc[4][8];                     // [rq = rr*2+q][local oc]; lanes=(px2q,px2q+1)
    #pragma unroll
    for (int rq = 0; rq < 4; rq++)
        #pragma unroll
        for (int o = 0; o < 8; o++) acc[rq][o] = 0ull;

    const unsigned fw0 = (unsigned)__cvta_generic_to_shared(sF)
                       + (unsigned)((2 * ty * SPITCH + 4 * tx) * 4);
    const unsigned ww0 = (unsigned)__cvta_generic_to_shared(sWk)
                       + (unsigned)(4 * tz) * 16u;      // e base = 4*tz

    #pragma unroll 1
    for (int ky = 0; ky < 3; ky++) {
        __syncthreads();
        #pragma unroll
        for (int it = 0; it < 6; it++)
            sWk[tid + it * 256] = g_wd[ky * SWK_ENT + tid + it * 256];
        __syncthreads();

        #pragma unroll
        for (int kx = 0; kx < 3; kx++) {
            const int k = ky * 3 + kx;
            ull MA[4], MB[4];
            #pragma unroll
            for (int rq = 0; rq < 4; rq++) {
                unsigned lo = mm[(rq >> 1) * 4 + (rq & 1) * 2];
                unsigned hi = mm[(rq >> 1) * 4 + (rq & 1) * 2 + 1];
                unsigned aL = 0u - ((lo >> k) & 1u);
                unsigned aH = 0u - ((hi >> k) & 1u);
                unsigned bL = 0u - ((lo >> (k + 16)) & 1u);
                unsigned bH = 0u - ((hi >> (k + 16)) & 1u);
                MA[rq] = ((ull)aH << 32) | aL;
                MB[rq] = ((ull)bH << 32) | bL;
            }

            unsigned fa = fw0 + (unsigned)(ky * SPITCH * 4);
            unsigned wa = ww0 + (unsigned)(kx * 512);

            #pragma unroll 1
            for (int i = 0; i < CCH; i++) {
                // two rows, 6-float windows f0..f5 at cols 4tx..4tx+5
                ull Pa01, Pa23, Pa45, Pb01, Pb23, Pb45;
                asm("ld.shared.v2.b64 {%0,%1},[%2];" : "=l"(Pa01), "=l"(Pa23) : "r"(fa));
                asm("ld.shared.b64 %0,[%1];" : "=l"(Pa45) : "r"(fa + 16));
                asm("ld.shared.v2.b64 {%0,%1},[%2];" : "=l"(Pb01), "=l"(Pb23) : "r"(fa + SPITCH * 4));
                asm("ld.shared.b64 %0,[%1];" : "=l"(Pb45) : "r"(fa + SPITCH * 4 + 16));

                ull Q[4];   // [rq]: pair values at this kx
                if (kx == 0) { Q[0] = Pa01; Q[1] = Pa23; Q[2] = Pb01; Q[3] = Pb23; }
                else if (kx == 2) { Q[0] = Pa23; Q[1] = Pa45; Q[2] = Pb23; Q[3] = Pb45; }
                else {
                    unsigned a0,a1,a2,a3,a4,a5,b0,b1,b2,b3,b4,b5;
                    asm("mov.b64 {%0,%1},%2;" : "=r"(a0), "=r"(a1) : "l"(Pa01));
                    asm("mov.b64 {%0,%1},%2;" : "=r"(a2), "=r"(a3) : "l"(Pa23));
                    asm("mov.b64 {%0,%1},%2;" : "=r"(a4), "=r"(a5) : "l"(Pa45));
                    asm("mov.b64 {%0,%1},%2;" : "=r"(b0), "=r"(b1) : "l"(Pb01));
                    asm("mov.b64 {%0,%1},%2;" : "=r"(b2), "=r"(b3) : "l"(Pb23));
                    asm("mov.b64 {%0,%1},%2;" : "=r"(b4), "=r"(b5) : "l"(Pb45));
                    asm("mov.b64 %0,{%1,%2};" : "=l"(Q[0]) : "r"(a1), "r"(a2));
                    asm("mov.b64 %0,{%1,%2};" : "=l"(Q[1]) : "r"(a3), "r"(a4));
                    asm("mov.b64 %0,{%1,%2};" : "=l"(Q[2]) : "r"(b1), "r"(b2));
                    asm("mov.b64 %0,{%1,%2};" : "=l"(Q[3]) : "r"(b3), "r"(b4));
                }

                ull GA0 = Q[0] & MA[0], GA1 = Q[1] & MA[1];
                ull GA2 = Q[2] & MA[2], GA3 = Q[3] & MA[3];
                ull GB0 = Q[0] & MB[0], GB1 = Q[1] & MB[1];
                ull GB2 = Q[2] & MB[2], GB3 = Q[3] & MB[3];

                #pragma unroll
                for (int j = 0; j < 4; j++) {     // slice A (s=0)
                    ull u, v;
                    asm("ld.shared.v2.b64 {%0,%1},[%2];"
                        : "=l"(u), "=l"(v) : "r"(wa + (unsigned)(j * 16)));
                    asm("fma.rn.f32x2 %0,%1,%2,%0;" : "+l"(acc[0][2*j])   : "l"(GA0), "l"(u));
                    asm("fma.rn.f32x2 %0,%1,%2,%0;" : "+l"(acc[0][2*j+1]) : "l"(GA0), "l"(v));
                    asm("fma.rn.f32x2 %0,%1,%2,%0;" : "+l"(acc[1][2*j])   : "l"(GA1), "l"(u));
                    asm("fma.rn.f32x2 %0,%1,%2,%0;" : "+l"(acc[1][2*j+1]) : "l"(GA1), "l"(v));
                    asm("fma.rn.f32x2 %0,%1,%2,%0;" : "+l"(acc[2][2*j])   : "l"(GA2), "l"(u));
                    asm("fma.rn.f32x2 %0,%1,%2,%0;" : "+l"(acc[2][2*j+1]) : "l"(GA2), "l"(v));
                    asm("fma.rn.f32x2 %0,%1,%2,%0;" : "+l"(acc[3][2*j])   : "l"(GA3), "l"(u));
                    asm("fma.rn.f32x2 %0,%1,%2,%0;" : "+l"(acc[3][2*j+1]) : "l"(GA3), "l"(v));
                }
                #pragma unroll
                for (int j = 0; j < 4; j++) {     // slice B (s=1, +256B)
                    ull u, v;
                    asm("ld.shared.v2.b64 {%0,%1},[%2];"
                        : "=l"(u), "=l"(v) : "r"(wa + (unsigned)(256 + j * 16)));
                    asm("fma.rn.f32x2 %0,%1,%2,%0;" : "+l"(acc[0][2*j])   : "l"(GB0), "l"(u));
                    asm("fma.rn.f32x2 %0,%1,%2,%0;" : "+l"(acc[0][2*j+1]) : "l"(GB0), "l"(v));
                    asm("fma.rn.f32x2 %0,%1,%2,%0;" : "+l"(acc[1][2*j])   : "l"(GB1), "l"(u));
                    asm("fma.rn.f32x2 %0,%1,%2,%0;" : "+l"(acc[1][2*j+1]) : "l"(GB1), "l"(v));
                    asm("fma.rn.f32x2 %0,%1,%2,%0;" : "+l"(acc[2][2*j])   : "l"(GB2), "l"(u));
                    asm("fma.rn.f32x2 %0,%1,%2,%0;" : "+l"(acc[2][2*j+1]) : "l"(GB2), "l"(v));
                    asm("fma.rn.f32x2 %0,%1,%2,%0;" : "+l"(acc[3][2*j])   : "l"(GB3), "l"(u));
                    asm("fma.rn.f32x2 %0,%1,%2,%0;" : "+l"(acc[3][2*j+1]) : "l"(GB3), "l"(v));
                }
                fa += FT_ROWS * SPITCH * 4;     // next channel (2720 B)
                wa += 1536;                     // next i block (96 entries)
            }
        }
    }

    // ---- epilogue: row rr, cols 4tx..4tx+3 from pairs (rr*2, rr*2+1) ----
    const int gx = x0 + 4 * tx;
    #pragma unroll
    for (int o = 0; o < 8; o++)
        #pragma unroll
        for (int rr = 0; rr < 2; rr++) {
            float2 q0 = *reinterpret_cast<float2*>(&acc[rr * 2][o]);
            float2 q1 = *reinterpret_cast<float2*>(&acc[rr * 2 + 1][o]);
            float4 st = make_float4(q0.x, q0.y, q1.x, q1.y);
            int gy = y0 + 2 * ty + rr;
            size_t off = (((size_t)(b * OCC + 8 * tz + o) * HH + gy) * WW) + gx;
            *reinterpret_cast<float4*>(out + off) = st;
        }
}

extern "C" void kernel_launch(void* const* d_in, const int* in_sizes, int n_in,
                              void* d_out, int out_size)
{
    const float* feat  = (const float*)d_in[0];
    const int*   depth = (const int*)d_in[1];
    const float* wgt   = (const float*)d_in[2];
    float* out = (float*)d_out;

    cudaFuncSetAttribute(depconv3d_kernel,
                         cudaFuncAttributeMaxDynamicSharedMemorySize, SMEM_TOTAL);

    pack_weights_kernel<<<(SW_ENT + 255) / 256, 256>>>(wgt);

    dim3 block(16, 4, 4);
    dim3 grid(WW / TW, HH / TH, 4);
    depconv3d_kernel<<<grid, block, SMEM_TOTAL>>>(feat, depth, out);
}